// round 12
// baseline (speedup 1.0000x reference)
#include <cuda_runtime.h>
#include <cuda_fp16.h>
#include <cstdint>

// ============================================================================
// out[M,N] = X[M,K] @ sign(W)[N,K]^T + bias[N],  M=N=K=4096, fp32.
// sm_103 plain PTX target => legacy mma.sync fp16 path.
// History: dual bf16 711us (R3); s8 IMMA banned (R4); fp16 412us (R6);
// 2 CTA/SM 356us (R7); 4-warp 64x64, 3-stage, 2 barriers 340us (R8 BEST);
// BN=64 3CTA 359us (R9); 1-barrier 363us (R10); SW-pipelined frags 355us (R11).
// R12: SAME 128x128 tile / 4 warps / 2 barriers, but 2-stage pipeline
// (64KB smem/CTA) => 3 CTAs/SM. L2-neutral occupancy increase: 3 HMMA
// streams per SMSP + elastic wave-tail. Regs capped via launch_bounds(128,3).
// ============================================================================

static constexpr int MM = 4096;
static constexpr int NN = 4096;
static constexpr int KK = 4096;

static constexpr int BM = 128;
static constexpr int BN = 128;
static constexpr int BK = 64;            // 64 fp16 = 128B row
static constexpr int STAGES = 2;
static constexpr int CHUNKS = KK / BK;   // 64
static constexpr int THREADS = 128;      // 4 warps: 2 (M) x 2 (N), warp 64x64

// SMEM stage layout (bytes)
static constexpr int A_BYTES = BM * 128;           // 16384
static constexpr int B_BYTES = BN * 128;           // 16384
static constexpr int A_OFF = 0;
static constexpr int B_OFF = A_BYTES;
static constexpr int STAGE_BYTES = A_BYTES + B_BYTES;   // 32768
static constexpr int SMEM_TOTAL = STAGES * STAGE_BYTES; // 65536

// ---------------------------------------------------------------------------
// Scratch (allocation-free)
// ---------------------------------------------------------------------------
__device__ __align__(1024) __half g_xa[(size_t)MM * KK];
__device__ __align__(1024) __half g_wb[(size_t)NN * KK];

// ---------------------------------------------------------------------------
// helpers
// ---------------------------------------------------------------------------
__device__ __forceinline__ uint32_t smem_u32(const void* p) {
    uint32_t a;
    asm("{ .reg .u64 t; cvta.to.shared.u64 t, %1; cvt.u32.u64 %0, t; }"
        : "=r"(a) : "l"(p));
    return a;
}

#define CP_ASYNC_16(dst, src) \
    asm volatile("cp.async.cg.shared.global [%0], [%1], 16;" \
        :: "r"(dst), "l"(src) : "memory")
#define CP_ASYNC_COMMIT() asm volatile("cp.async.commit_group;" ::: "memory")
#define CP_ASYNC_WAIT_1() asm volatile("cp.async.wait_group 1;" ::: "memory")

__device__ __forceinline__ void ldmatrix_x4(uint32_t& r0, uint32_t& r1,
                                            uint32_t& r2, uint32_t& r3,
                                            uint32_t addr) {
    asm volatile("ldmatrix.sync.aligned.m8n8.x4.shared.b16 {%0,%1,%2,%3}, [%4];"
                 : "=r"(r0), "=r"(r1), "=r"(r2), "=r"(r3) : "r"(addr));
}

__device__ __forceinline__ void mma_f16(float* d, const uint32_t* a,
                                        uint32_t b0, uint32_t b1) {
    asm volatile(
        "mma.sync.aligned.m16n8k16.row.col.f32.f16.f16.f32 "
        "{%0,%1,%2,%3}, {%4,%5,%6,%7}, {%8,%9}, {%0,%1,%2,%3};"
        : "+f"(d[0]), "+f"(d[1]), "+f"(d[2]), "+f"(d[3])
        : "r"(a[0]), "r"(a[1]), "r"(a[2]), "r"(a[3]), "r"(b0), "r"(b1));
}

// ---------------------------------------------------------------------------
// Conversion kernels
// ---------------------------------------------------------------------------
__global__ void __launch_bounds__(256) convert_x_kernel(
    const float4* __restrict__ x, uint2* __restrict__ xa) {
    int i = blockIdx.x * 256 + threadIdx.x;
    float4 v = x[i];
    __half2 p01 = __floats2half2_rn(v.x, v.y);
    __half2 p23 = __floats2half2_rn(v.z, v.w);
    uint2 p;
    p.x = *reinterpret_cast<uint32_t*>(&p01);
    p.y = *reinterpret_cast<uint32_t*>(&p23);
    xa[i] = p;
}

__global__ void __launch_bounds__(256) convert_w_kernel(
    const float4* __restrict__ w, uint2* __restrict__ wb) {
    int i = blockIdx.x * 256 + threadIdx.x;
    float4 v = w[i];
    float s0 = (v.x > 0.f) ? 1.f : ((v.x < 0.f) ? -1.f : 0.f);
    float s1 = (v.y > 0.f) ? 1.f : ((v.y < 0.f) ? -1.f : 0.f);
    float s2 = (v.z > 0.f) ? 1.f : ((v.z < 0.f) ? -1.f : 0.f);
    float s3 = (v.w > 0.f) ? 1.f : ((v.w < 0.f) ? -1.f : 0.f);
    __half2 p01 = __floats2half2_rn(s0, s1);
    __half2 p23 = __floats2half2_rn(s2, s3);
    uint2 p;
    p.x = *reinterpret_cast<uint32_t*>(&p01);
    p.y = *reinterpret_cast<uint32_t*>(&p23);
    wb[i] = p;
}

// ---------------------------------------------------------------------------
// GEMM kernel (single fp16 pass, 4 warps, 3 CTAs/SM, 2-stage pipeline)
// ---------------------------------------------------------------------------
__global__ void __launch_bounds__(THREADS, 3)
bingemm_kernel(const __half* __restrict__ xa,
               const __half* __restrict__ wb,
               const float* __restrict__ bias,
               float* __restrict__ out) {
    extern __shared__ __align__(1024) char smem[];
    const uint32_t sb = smem_u32(smem);

    const int tid = threadIdx.x;
    const int wid = tid >> 5;
    const int lane = tid & 31;
    const int warp_m = wid & 1;    // 0..1 -> 64 rows
    const int warp_n = wid >> 1;   // 0..1 -> 64 cols
    const int m0 = blockIdx.y * BM;
    const int n0 = blockIdx.x * BN;

    // --- cp.async tile loader (row = 128B = 8 x 16B chunks, xor swizzle) ---
    const int ld_row = tid >> 3;   // 0..15
    const int ld_chunk = tid & 7;  // 0..7

    auto load_stage = [&](int stage, int c) {
        const uint32_t sbase = sb + stage * STAGE_BYTES;
        const int k0 = c * BK;
        #pragma unroll
        for (int i = 0; i < 8; i++) {
            int row = i * 16 + ld_row;
            uint32_t soff = row * 128 + ((ld_chunk ^ (row & 7)) << 4);
            CP_ASYNC_16(sbase + A_OFF + soff,
                        xa + (size_t)(m0 + row) * KK + k0 + ld_chunk * 8);
        }
        #pragma unroll
        for (int i = 0; i < 8; i++) {
            int row = i * 16 + ld_row;
            uint32_t soff = row * 128 + ((ld_chunk ^ (row & 7)) << 4);
            CP_ASYNC_16(sbase + B_OFF + soff,
                        wb + (size_t)(n0 + row) * KK + k0 + ld_chunk * 8);
        }
    };

    // prologue: both stages in flight
    load_stage(0, 0); CP_ASYNC_COMMIT();
    load_stage(1, 1); CP_ASYNC_COMMIT();

    // --- ldmatrix per-thread address components ---
    const int mt = lane >> 3;            // matrix index 0..3
    const int lrow = lane & 7;
    // A mats: (m+0,kc0) (m+8,kc0) (m+0,kc1) (m+8,kc1)
    const int a_row = warp_m * 64 + lrow + ((mt & 1) << 3);   // + mi*16
    const int a_koff = mt >> 1;
    // B mats: (n+0,kc0) (n+0,kc1) (n+8,kc0) (n+8,kc1)
    const int b_row = warp_n * 64 + lrow + ((mt >> 1) << 3);  // + nj2*16
    const int b_koff = mt & 1;

    float acc[4][8][4];                  // mi, nj (8 x n8), quad
    #pragma unroll
    for (int mi = 0; mi < 4; mi++)
        #pragma unroll
        for (int nj = 0; nj < 8; nj++)
            #pragma unroll
            for (int q = 0; q < 4; q++) acc[mi][nj][q] = 0.f;

    for (int c = 0; c < CHUNKS; c++) {
        // Stage c&1 holds chunk c's data once <=1 group is outstanding.
        CP_ASYNC_WAIT_1();
        __syncthreads();

        const uint32_t sbase = sb + (c & 1) * STAGE_BYTES;

        #pragma unroll
        for (int ks = 0; ks < 4; ks++) {
            // B fragments: 4 x ldmatrix.x4 -> 8 n8 slices
            uint32_t b[4][4];
            #pragma unroll
            for (int nj2 = 0; nj2 < 4; nj2++) {
                int row = b_row + nj2 * 16;
                int kch = ks * 2 + b_koff;
                uint32_t off = row * 128 + ((kch ^ (row & 7)) << 4);
                ldmatrix_x4(b[nj2][0], b[nj2][1], b[nj2][2], b[nj2][3],
                            sbase + B_OFF + off);
            }
            // A fragments just-in-time per 16-row slice
            #pragma unroll
            for (int mi = 0; mi < 4; mi++) {
                int row = a_row + mi * 16;
                int kch = ks * 2 + a_koff;
                uint32_t off = row * 128 + ((kch ^ (row & 7)) << 4);
                uint32_t a[4];
                ldmatrix_x4(a[0], a[1], a[2], a[3], sbase + A_OFF + off);
                #pragma unroll
                for (int nj2 = 0; nj2 < 4; nj2++) {
                    mma_f16(acc[mi][nj2 * 2 + 0], a, b[nj2][0], b[nj2][1]);
                    mma_f16(acc[mi][nj2 * 2 + 1], a, b[nj2][2], b[nj2][3]);
                }
            }
        }
        // Barrier before refilling the stage we just consumed.
        __syncthreads();
        if (c + 2 < CHUNKS) {
            load_stage((c + 2) & 1, c + 2);
        }
        CP_ASYNC_COMMIT();
    }

    // --- epilogue: += bias, write fp32 ---
    const int qcol = (lane & 3) * 2;
    float2 bv[8];
    #pragma unroll
    for (int nj = 0; nj < 8; nj++)
        bv[nj] = *reinterpret_cast<const float2*>(
            bias + n0 + warp_n * 64 + nj * 8 + qcol);

    #pragma unroll
    for (int mi = 0; mi < 4; mi++) {
        int r0 = m0 + warp_m * 64 + mi * 16 + (lane >> 2);
        float* p0 = out + (size_t)r0 * NN + n0 + warp_n * 64 + qcol;
        float* p1 = p0 + 8 * NN;
        #pragma unroll
        for (int nj = 0; nj < 8; nj++) {
            float2 v0, v1;
            v0.x = acc[mi][nj][0] + bv[nj].x;
            v0.y = acc[mi][nj][1] + bv[nj].y;
            v1.x = acc[mi][nj][2] + bv[nj].x;
            v1.y = acc[mi][nj][3] + bv[nj].y;
            *reinterpret_cast<float2*>(p0 + nj * 8) = v0;
            *reinterpret_cast<float2*>(p1 + nj * 8) = v1;
        }
    }
}

// ---------------------------------------------------------------------------
// Host launch
// ---------------------------------------------------------------------------
extern "C" void kernel_launch(void* const* d_in, const int* in_sizes, int n_in,
                              void* d_out, int out_size) {
    const float* x    = (const float*)d_in[0];
    const float* w    = (const float*)d_in[1];
    const float* bias = (const float*)d_in[2];
    float* out = (float*)d_out;

    void *p_xa = nullptr, *p_wb = nullptr;
    cudaGetSymbolAddress(&p_xa, g_xa);
    cudaGetSymbolAddress(&p_wb, g_wb);

    const int n4 = MM * KK / 4;
    convert_x_kernel<<<n4 / 256, 256>>>((const float4*)x, (uint2*)p_xa);
    convert_w_kernel<<<n4 / 256, 256>>>((const float4*)w, (uint2*)p_wb);

    static bool attr_set = false;
    if (!attr_set) {
        cudaFuncSetAttribute(bingemm_kernel,
                             cudaFuncAttributeMaxDynamicSharedMemorySize, SMEM_TOTAL);
        attr_set = true;
    }

    dim3 grid(NN / BN, MM / BM);  // (32, 32) = 1024 CTAs
    bingemm_kernel<<<grid, THREADS, SMEM_TOTAL>>>(
        (const __half*)p_xa, (const __half*)p_wb, bias, out);
}

// round 13
// speedup vs baseline: 1.0854x; 1.0854x over previous
#include <cuda_runtime.h>
#include <cuda_fp16.h>
#include <cstdint>

// ============================================================================
// out[M,N] = X[M,K] @ sign(W)[N,K]^T + bias[N],  M=N=K=4096, fp32.
// sm_103 plain PTX target => legacy mma.sync fp16 path.
// History: dual bf16 711us (R3); s8 IMMA banned (R4); fp16 412us (R6);
// 2 CTA/SM 356us (R7); 4-warp 64x64, 3-stage, 2 barriers 340us (R8 BEST);
// R9-R12 scheduling/occupancy variants all REGRESSED (355-363us).
// R13: keep R8's mainloop byte-identical; make the kernel PERSISTENT
// (grid = 2*SMs, each CTA loops tiles) with a global chunk counter so the
// 3-stage cp.async pipeline flows ACROSS tile boundaries: next tile's loads
// are in flight during this tile's epilogue. Converts fused into one launch.
// ============================================================================

static constexpr int MM = 4096;
static constexpr int NN = 4096;
static constexpr int KK = 4096;

static constexpr int BM = 128;
static constexpr int BN = 128;
static constexpr int BK = 64;            // 64 fp16 = 128B row
static constexpr int STAGES = 3;
static constexpr int CPT = KK / BK;      // 64 chunks per tile
static constexpr int THREADS = 128;      // 4 warps: 2 (M) x 2 (N), warp 64x64
static constexpr int NTILES = (MM / BM) * (NN / BN);  // 1024

// SMEM stage layout (bytes)
static constexpr int A_BYTES = BM * 128;           // 16384
static constexpr int B_BYTES = BN * 128;           // 16384
static constexpr int A_OFF = 0;
static constexpr int B_OFF = A_BYTES;
static constexpr int STAGE_BYTES = A_BYTES + B_BYTES;   // 32768
static constexpr int SMEM_TOTAL = STAGES * STAGE_BYTES; // 98304

// ---------------------------------------------------------------------------
// Scratch (allocation-free)
// ---------------------------------------------------------------------------
__device__ __align__(1024) __half g_xa[(size_t)MM * KK];
__device__ __align__(1024) __half g_wb[(size_t)NN * KK];

// ---------------------------------------------------------------------------
// helpers
// ---------------------------------------------------------------------------
__device__ __forceinline__ uint32_t smem_u32(const void* p) {
    uint32_t a;
    asm("{ .reg .u64 t; cvta.to.shared.u64 t, %1; cvt.u32.u64 %0, t; }"
        : "=r"(a) : "l"(p));
    return a;
}

#define CP_ASYNC_16(dst, src) \
    asm volatile("cp.async.cg.shared.global [%0], [%1], 16;" \
        :: "r"(dst), "l"(src) : "memory")
#define CP_ASYNC_COMMIT() asm volatile("cp.async.commit_group;" ::: "memory")
#define CP_ASYNC_WAIT_1() asm volatile("cp.async.wait_group 1;" ::: "memory")

__device__ __forceinline__ void ldmatrix_x4(uint32_t& r0, uint32_t& r1,
                                            uint32_t& r2, uint32_t& r3,
                                            uint32_t addr) {
    asm volatile("ldmatrix.sync.aligned.m8n8.x4.shared.b16 {%0,%1,%2,%3}, [%4];"
                 : "=r"(r0), "=r"(r1), "=r"(r2), "=r"(r3) : "r"(addr));
}

__device__ __forceinline__ void mma_f16(float* d, const uint32_t* a,
                                        uint32_t b0, uint32_t b1) {
    asm volatile(
        "mma.sync.aligned.m16n8k16.row.col.f32.f16.f16.f32 "
        "{%0,%1,%2,%3}, {%4,%5,%6,%7}, {%8,%9}, {%0,%1,%2,%3};"
        : "+f"(d[0]), "+f"(d[1]), "+f"(d[2]), "+f"(d[3])
        : "r"(a[0]), "r"(a[1]), "r"(a[2]), "r"(a[3]), "r"(b0), "r"(b1));
}

// ---------------------------------------------------------------------------
// Fused conversion kernel: blocks [0, nb4) do X->fp16, [nb4, 2*nb4) do sign(W)
// ---------------------------------------------------------------------------
__global__ void __launch_bounds__(256) convert_fused_kernel(
    const float4* __restrict__ x, const float4* __restrict__ w,
    uint2* __restrict__ xa, uint2* __restrict__ wb, int nb4) {
    int b = blockIdx.x;
    if (b < nb4) {
        int i = b * 256 + threadIdx.x;
        float4 v = x[i];
        __half2 p01 = __floats2half2_rn(v.x, v.y);
        __half2 p23 = __floats2half2_rn(v.z, v.w);
        uint2 p;
        p.x = *reinterpret_cast<uint32_t*>(&p01);
        p.y = *reinterpret_cast<uint32_t*>(&p23);
        xa[i] = p;
    } else {
        int i = (b - nb4) * 256 + threadIdx.x;
        float4 v = w[i];
        float s0 = (v.x > 0.f) ? 1.f : ((v.x < 0.f) ? -1.f : 0.f);
        float s1 = (v.y > 0.f) ? 1.f : ((v.y < 0.f) ? -1.f : 0.f);
        float s2 = (v.z > 0.f) ? 1.f : ((v.z < 0.f) ? -1.f : 0.f);
        float s3 = (v.w > 0.f) ? 1.f : ((v.w < 0.f) ? -1.f : 0.f);
        __half2 p01 = __floats2half2_rn(s0, s1);
        __half2 p23 = __floats2half2_rn(s2, s3);
        uint2 p;
        p.x = *reinterpret_cast<uint32_t*>(&p01);
        p.y = *reinterpret_cast<uint32_t*>(&p23);
        wb[i] = p;
    }
}

// ---------------------------------------------------------------------------
// Persistent GEMM kernel (single fp16 pass, 4 warps, 2 CTAs/SM)
// ---------------------------------------------------------------------------
__global__ void __launch_bounds__(THREADS, 2)
bingemm_kernel(const __half* __restrict__ xa,
               const __half* __restrict__ wb,
               const float* __restrict__ bias,
               float* __restrict__ out) {
    extern __shared__ __align__(1024) char smem[];
    const uint32_t sb = smem_u32(smem);

    const int tid = threadIdx.x;
    const int wid = tid >> 5;
    const int lane = tid & 31;
    const int warp_m = wid & 1;    // 0..1 -> 64 rows
    const int warp_n = wid >> 1;   // 0..1 -> 64 cols
    const int G = gridDim.x;

    // tiles for this CTA: blockIdx.x, +G, +2G, ...
    const int ntiles = (NTILES - 1 - (int)blockIdx.x) / G + 1;
    const int ntotal = ntiles * CPT;   // global chunk count

    // --- cp.async tile loader (row = 128B = 8 x 16B chunks, xor swizzle) ---
    const int ld_row = tid >> 3;   // 0..15
    const int ld_chunk = tid & 7;  // 0..7

    auto load_gchunk = [&](int stage, int gc) {
        const int tile = blockIdx.x + (gc >> 6) * G;   // gc/CPT
        const int m0 = (tile >> 5) * BM;               // tile / 32
        const int n0 = (tile & 31) * BN;               // tile % 32
        const int k0 = (gc & 63) * BK;
        const uint32_t sbase = sb + stage * STAGE_BYTES;
        #pragma unroll
        for (int i = 0; i < 8; i++) {
            int row = i * 16 + ld_row;
            uint32_t soff = row * 128 + ((ld_chunk ^ (row & 7)) << 4);
            CP_ASYNC_16(sbase + A_OFF + soff,
                        xa + (size_t)(m0 + row) * KK + k0 + ld_chunk * 8);
        }
        #pragma unroll
        for (int i = 0; i < 8; i++) {
            int row = i * 16 + ld_row;
            uint32_t soff = row * 128 + ((ld_chunk ^ (row & 7)) << 4);
            CP_ASYNC_16(sbase + B_OFF + soff,
                        wb + (size_t)(n0 + row) * KK + k0 + ld_chunk * 8);
        }
    };

    // prologue: 2 stages in flight (only once per CTA, not per tile)
    load_gchunk(0, 0); CP_ASYNC_COMMIT();
    load_gchunk(1, 1); CP_ASYNC_COMMIT();

    // --- ldmatrix per-thread address components ---
    const int mt = lane >> 3;            // matrix index 0..3
    const int lrow = lane & 7;
    const int a_row = warp_m * 64 + lrow + ((mt & 1) << 3);   // + mi*16
    const int a_koff = mt >> 1;
    const int b_row = warp_n * 64 + lrow + ((mt >> 1) << 3);  // + nj2*16
    const int b_koff = mt & 1;

    float acc[4][8][4];                  // mi, nj (8 x n8), quad
    #pragma unroll
    for (int mi = 0; mi < 4; mi++)
        #pragma unroll
        for (int nj = 0; nj < 8; nj++)
            #pragma unroll
            for (int q = 0; q < 4; q++) acc[mi][nj][q] = 0.f;

    const int qcol = (lane & 3) * 2;

    for (int ti = 0; ti < ntiles; ti++) {
        // ---- mainloop for this tile: EXACT R8 structure, global chunk idx ----
        for (int c = 0; c < CPT; c++) {
            const int gc = ti * CPT + c;
            CP_ASYNC_WAIT_1();
            __syncthreads();
            if (gc + 2 < ntotal) load_gchunk((gc + 2) % STAGES, gc + 2);
            CP_ASYNC_COMMIT();

            const uint32_t sbase = sb + (gc % STAGES) * STAGE_BYTES;

            #pragma unroll
            for (int ks = 0; ks < 4; ks++) {
                uint32_t b[4][4];
                #pragma unroll
                for (int nj2 = 0; nj2 < 4; nj2++) {
                    int row = b_row + nj2 * 16;
                    int kch = ks * 2 + b_koff;
                    uint32_t off = row * 128 + ((kch ^ (row & 7)) << 4);
                    ldmatrix_x4(b[nj2][0], b[nj2][1], b[nj2][2], b[nj2][3],
                                sbase + B_OFF + off);
                }
                #pragma unroll
                for (int mi = 0; mi < 4; mi++) {
                    int row = a_row + mi * 16;
                    int kch = ks * 2 + a_koff;
                    uint32_t off = row * 128 + ((kch ^ (row & 7)) << 4);
                    uint32_t a[4];
                    ldmatrix_x4(a[0], a[1], a[2], a[3], sbase + A_OFF + off);
                    #pragma unroll
                    for (int nj2 = 0; nj2 < 4; nj2++) {
                        mma_f16(acc[mi][nj2 * 2 + 0], a, b[nj2][0], b[nj2][1]);
                        mma_f16(acc[mi][nj2 * 2 + 1], a, b[nj2][2], b[nj2][3]);
                    }
                }
            }
            __syncthreads();
        }

        // ---- epilogue for this tile (next tile's loads already in flight) ----
        {
            const int tile = blockIdx.x + ti * G;
            const int m0 = (tile >> 5) * BM;
            const int n0 = (tile & 31) * BN;

            #pragma unroll
            for (int mi = 0; mi < 4; mi++) {
                int r0 = m0 + warp_m * 64 + mi * 16 + (lane >> 2);
                float* p0 = out + (size_t)r0 * NN + n0 + warp_n * 64 + qcol;
                float* p1 = p0 + 8 * NN;
                #pragma unroll
                for (int nj = 0; nj < 8; nj++) {
                    float2 bv = *reinterpret_cast<const float2*>(
                        bias + n0 + warp_n * 64 + nj * 8 + qcol);
                    float2 v0, v1;
                    v0.x = acc[mi][nj][0] + bv.x;
                    v0.y = acc[mi][nj][1] + bv.y;
                    v1.x = acc[mi][nj][2] + bv.x;
                    v1.y = acc[mi][nj][3] + bv.y;
                    *reinterpret_cast<float2*>(p0 + nj * 8) = v0;
                    *reinterpret_cast<float2*>(p1 + nj * 8) = v1;
                    acc[mi][nj][0] = 0.f; acc[mi][nj][1] = 0.f;
                    acc[mi][nj][2] = 0.f; acc[mi][nj][3] = 0.f;
                }
            }
        }
    }
}

// ---------------------------------------------------------------------------
// Host launch
// ---------------------------------------------------------------------------
extern "C" void kernel_launch(void* const* d_in, const int* in_sizes, int n_in,
                              void* d_out, int out_size) {
    const float* x    = (const float*)d_in[0];
    const float* w    = (const float*)d_in[1];
    const float* bias = (const float*)d_in[2];
    float* out = (float*)d_out;

    void *p_xa = nullptr, *p_wb = nullptr;
    cudaGetSymbolAddress(&p_xa, g_xa);
    cudaGetSymbolAddress(&p_wb, g_wb);

    const int n4 = MM * KK / 4;          // float4 count per tensor
    const int nb4 = n4 / 256;            // blocks per tensor
    convert_fused_kernel<<<2 * nb4, 256>>>((const float4*)x, (const float4*)w,
                                           (uint2*)p_xa, (uint2*)p_wb, nb4);

    static bool attr_set = false;
    if (!attr_set) {
        cudaFuncSetAttribute(bingemm_kernel,
                             cudaFuncAttributeMaxDynamicSharedMemorySize, SMEM_TOTAL);
        attr_set = true;
    }

    int sms = 148;
    cudaDeviceGetAttribute(&sms, cudaDevAttrMultiProcessorCount, 0);
    const int G = 2 * sms;               // persistent grid: 2 CTAs per SM

    bingemm_kernel<<<G, THREADS, SMEM_TOTAL>>>(
        (const __half*)p_xa, (const __half*)p_wb, bias, out);
}

// round 14
// speedup vs baseline: 1.1189x; 1.0309x over previous
#include <cuda_runtime.h>
#include <cuda_fp16.h>
#include <cstdint>

// ============================================================================
// out[M,N] = X[M,K] @ sign(W)[N,K]^T + bias[N],  M=N=K=4096, fp32.
// sm_103 plain PTX target => legacy mma.sync fp16 path.
// History: dual bf16 711us (R3); s8 IMMA banned (R4); fp16 412us (R6);
// 2 CTA/SM 356 (R7); 4-warp 64x64 3-stage 340 (R8); R9-R12 variants all
// regressed; persistent 334us (R13 BEST; ncu: tensor 75.5%, DRAM 4%).
// R14: (a) issue chunk c+2's cp.asyncs BEFORE wait_group (LSU burst hidden
// under the pipeline wait; wait depth 1->2), (b) convert kernels get MLP=4
// (4 independent float4 per thread; they were latency-bound at 57% HBM).
// ============================================================================

static constexpr int MM = 4096;
static constexpr int NN = 4096;
static constexpr int KK = 4096;

static constexpr int BM = 128;
static constexpr int BN = 128;
static constexpr int BK = 64;            // 64 fp16 = 128B row
static constexpr int STAGES = 3;
static constexpr int CPT = KK / BK;      // 64 chunks per tile
static constexpr int THREADS = 128;      // 4 warps: 2 (M) x 2 (N), warp 64x64
static constexpr int NTILES = (MM / BM) * (NN / BN);  // 1024

// SMEM stage layout (bytes)
static constexpr int A_BYTES = BM * 128;           // 16384
static constexpr int B_BYTES = BN * 128;           // 16384
static constexpr int A_OFF = 0;
static constexpr int B_OFF = A_BYTES;
static constexpr int STAGE_BYTES = A_BYTES + B_BYTES;   // 32768
static constexpr int SMEM_TOTAL = STAGES * STAGE_BYTES; // 98304

// ---------------------------------------------------------------------------
// Scratch (allocation-free)
// ---------------------------------------------------------------------------
__device__ __align__(1024) __half g_xa[(size_t)MM * KK];
__device__ __align__(1024) __half g_wb[(size_t)NN * KK];

// ---------------------------------------------------------------------------
// helpers
// ---------------------------------------------------------------------------
__device__ __forceinline__ uint32_t smem_u32(const void* p) {
    uint32_t a;
    asm("{ .reg .u64 t; cvta.to.shared.u64 t, %1; cvt.u32.u64 %0, t; }"
        : "=r"(a) : "l"(p));
    return a;
}

#define CP_ASYNC_16(dst, src) \
    asm volatile("cp.async.cg.shared.global [%0], [%1], 16;" \
        :: "r"(dst), "l"(src) : "memory")
#define CP_ASYNC_COMMIT() asm volatile("cp.async.commit_group;" ::: "memory")
#define CP_ASYNC_WAIT_2() asm volatile("cp.async.wait_group 2;" ::: "memory")

__device__ __forceinline__ void ldmatrix_x4(uint32_t& r0, uint32_t& r1,
                                            uint32_t& r2, uint32_t& r3,
                                            uint32_t addr) {
    asm volatile("ldmatrix.sync.aligned.m8n8.x4.shared.b16 {%0,%1,%2,%3}, [%4];"
                 : "=r"(r0), "=r"(r1), "=r"(r2), "=r"(r3) : "r"(addr));
}

__device__ __forceinline__ void mma_f16(float* d, const uint32_t* a,
                                        uint32_t b0, uint32_t b1) {
    asm volatile(
        "mma.sync.aligned.m16n8k16.row.col.f32.f16.f16.f32 "
        "{%0,%1,%2,%3}, {%4,%5,%6,%7}, {%8,%9}, {%0,%1,%2,%3};"
        : "+f"(d[0]), "+f"(d[1]), "+f"(d[2]), "+f"(d[3])
        : "r"(a[0]), "r"(a[1]), "r"(a[2]), "r"(a[3]), "r"(b0), "r"(b1));
}

// ---------------------------------------------------------------------------
// Fused conversion kernel, MLP=4: blocks [0,nbx) do X, [nbx,2*nbx) do sign(W).
// Each thread handles 4 independent float4s spaced n4/4 apart.
// ---------------------------------------------------------------------------
__global__ void __launch_bounds__(256) convert_fused_kernel(
    const float4* __restrict__ x, const float4* __restrict__ w,
    uint2* __restrict__ xa, uint2* __restrict__ wb, int nbx, int quarter) {
    const int b = blockIdx.x;
    if (b < nbx) {
        const int i = b * 256 + threadIdx.x;
        float4 v[4];
        #pragma unroll
        for (int k = 0; k < 4; k++) v[k] = x[i + k * quarter];
        #pragma unroll
        for (int k = 0; k < 4; k++) {
            __half2 p01 = __floats2half2_rn(v[k].x, v[k].y);
            __half2 p23 = __floats2half2_rn(v[k].z, v[k].w);
            uint2 p;
            p.x = *reinterpret_cast<uint32_t*>(&p01);
            p.y = *reinterpret_cast<uint32_t*>(&p23);
            xa[i + k * quarter] = p;
        }
    } else {
        const int i = (b - nbx) * 256 + threadIdx.x;
        float4 v[4];
        #pragma unroll
        for (int k = 0; k < 4; k++) v[k] = w[i + k * quarter];
        #pragma unroll
        for (int k = 0; k < 4; k++) {
            float s0 = (v[k].x > 0.f) ? 1.f : ((v[k].x < 0.f) ? -1.f : 0.f);
            float s1 = (v[k].y > 0.f) ? 1.f : ((v[k].y < 0.f) ? -1.f : 0.f);
            float s2 = (v[k].z > 0.f) ? 1.f : ((v[k].z < 0.f) ? -1.f : 0.f);
            float s3 = (v[k].w > 0.f) ? 1.f : ((v[k].w < 0.f) ? -1.f : 0.f);
            __half2 p01 = __floats2half2_rn(s0, s1);
            __half2 p23 = __floats2half2_rn(s2, s3);
            uint2 p;
            p.x = *reinterpret_cast<uint32_t*>(&p01);
            p.y = *reinterpret_cast<uint32_t*>(&p23);
            wb[i + k * quarter] = p;
        }
    }
}

// ---------------------------------------------------------------------------
// Persistent GEMM kernel (single fp16 pass, 4 warps, 2 CTAs/SM)
// ---------------------------------------------------------------------------
__global__ void __launch_bounds__(THREADS, 2)
bingemm_kernel(const __half* __restrict__ xa,
               const __half* __restrict__ wb,
               const float* __restrict__ bias,
               float* __restrict__ out) {
    extern __shared__ __align__(1024) char smem[];
    const uint32_t sb = smem_u32(smem);

    const int tid = threadIdx.x;
    const int wid = tid >> 5;
    const int lane = tid & 31;
    const int warp_m = wid & 1;    // 0..1 -> 64 rows
    const int warp_n = wid >> 1;   // 0..1 -> 64 cols
    const int G = gridDim.x;

    const int ntiles = (NTILES - 1 - (int)blockIdx.x) / G + 1;
    const int ntotal = ntiles * CPT;   // global chunk count

    // --- cp.async tile loader (row = 128B = 8 x 16B chunks, xor swizzle) ---
    const int ld_row = tid >> 3;   // 0..15
    const int ld_chunk = tid & 7;  // 0..7

    auto load_gchunk = [&](int stage, int gc) {
        const int tile = blockIdx.x + (gc >> 6) * G;   // gc/CPT
        const int m0 = (tile >> 5) * BM;               // tile / 32
        const int n0 = (tile & 31) * BN;               // tile % 32
        const int k0 = (gc & 63) * BK;
        const uint32_t sbase = sb + stage * STAGE_BYTES;
        #pragma unroll
        for (int i = 0; i < 8; i++) {
            int row = i * 16 + ld_row;
            uint32_t soff = row * 128 + ((ld_chunk ^ (row & 7)) << 4);
            CP_ASYNC_16(sbase + A_OFF + soff,
                        xa + (size_t)(m0 + row) * KK + k0 + ld_chunk * 8);
        }
        #pragma unroll
        for (int i = 0; i < 8; i++) {
            int row = i * 16 + ld_row;
            uint32_t soff = row * 128 + ((ld_chunk ^ (row & 7)) << 4);
            CP_ASYNC_16(sbase + B_OFF + soff,
                        wb + (size_t)(n0 + row) * KK + k0 + ld_chunk * 8);
        }
    };

    // prologue: 2 stages in flight (once per CTA)
    load_gchunk(0, 0); CP_ASYNC_COMMIT();
    load_gchunk(1, 1); CP_ASYNC_COMMIT();

    // --- ldmatrix per-thread address components ---
    const int mt = lane >> 3;            // matrix index 0..3
    const int lrow = lane & 7;
    const int a_row = warp_m * 64 + lrow + ((mt & 1) << 3);   // + mi*16
    const int a_koff = mt >> 1;
    const int b_row = warp_n * 64 + lrow + ((mt >> 1) << 3);  // + nj2*16
    const int b_koff = mt & 1;

    float acc[4][8][4];                  // mi, nj (8 x n8), quad
    #pragma unroll
    for (int mi = 0; mi < 4; mi++)
        #pragma unroll
        for (int nj = 0; nj < 8; nj++)
            #pragma unroll
            for (int q = 0; q < 4; q++) acc[mi][nj][q] = 0.f;

    const int qcol = (lane & 3) * 2;

    for (int ti = 0; ti < ntiles; ti++) {
        for (int c = 0; c < CPT; c++) {
            const int gc = ti * CPT + c;
            // Issue chunk gc+2's loads BEFORE waiting: stage (gc+2)%3 held
            // chunk gc-1, whose compute finished before the bottom sync of
            // the previous iteration. LSU burst now overlaps the wait.
            if (gc + 2 < ntotal) load_gchunk((gc + 2) % STAGES, gc + 2);
            CP_ASYNC_COMMIT();
            // Allow 2 outstanding groups (gc+1, gc+2) => chunk gc complete.
            CP_ASYNC_WAIT_2();
            __syncthreads();

            const uint32_t sbase = sb + (gc % STAGES) * STAGE_BYTES;

            #pragma unroll
            for (int ks = 0; ks < 4; ks++) {
                uint32_t b[4][4];
                #pragma unroll
                for (int nj2 = 0; nj2 < 4; nj2++) {
                    int row = b_row + nj2 * 16;
                    int kch = ks * 2 + b_koff;
                    uint32_t off = row * 128 + ((kch ^ (row & 7)) << 4);
                    ldmatrix_x4(b[nj2][0], b[nj2][1], b[nj2][2], b[nj2][3],
                                sbase + B_OFF + off);
                }
                #pragma unroll
                for (int mi = 0; mi < 4; mi++) {
                    int row = a_row + mi * 16;
                    int kch = ks * 2 + a_koff;
                    uint32_t off = row * 128 + ((kch ^ (row & 7)) << 4);
                    uint32_t a[4];
                    ldmatrix_x4(a[0], a[1], a[2], a[3], sbase + A_OFF + off);
                    #pragma unroll
                    for (int nj2 = 0; nj2 < 4; nj2++) {
                        mma_f16(acc[mi][nj2 * 2 + 0], a, b[nj2][0], b[nj2][1]);
                        mma_f16(acc[mi][nj2 * 2 + 1], a, b[nj2][2], b[nj2][3]);
                    }
                }
            }
            __syncthreads();
        }

        // ---- epilogue for this tile (next tile's loads already in flight) ----
        {
            const int tile = blockIdx.x + ti * G;
            const int m0 = (tile >> 5) * BM;
            const int n0 = (tile & 31) * BN;

            #pragma unroll
            for (int mi = 0; mi < 4; mi++) {
                int r0 = m0 + warp_m * 64 + mi * 16 + (lane >> 2);
                float* p0 = out + (size_t)r0 * NN + n0 + warp_n * 64 + qcol;
                float* p1 = p0 + 8 * NN;
                #pragma unroll
                for (int nj = 0; nj < 8; nj++) {
                    float2 bv = *reinterpret_cast<const float2*>(
                        bias + n0 + warp_n * 64 + nj * 8 + qcol);
                    float2 v0, v1;
                    v0.x = acc[mi][nj][0] + bv.x;
                    v0.y = acc[mi][nj][1] + bv.y;
                    v1.x = acc[mi][nj][2] + bv.x;
                    v1.y = acc[mi][nj][3] + bv.y;
                    *reinterpret_cast<float2*>(p0 + nj * 8) = v0;
                    *reinterpret_cast<float2*>(p1 + nj * 8) = v1;
                    acc[mi][nj][0] = 0.f; acc[mi][nj][1] = 0.f;
                    acc[mi][nj][2] = 0.f; acc[mi][nj][3] = 0.f;
                }
            }
        }
    }
}

// ---------------------------------------------------------------------------
// Host launch
// ---------------------------------------------------------------------------
extern "C" void kernel_launch(void* const* d_in, const int* in_sizes, int n_in,
                              void* d_out, int out_size) {
    const float* x    = (const float*)d_in[0];
    const float* w    = (const float*)d_in[1];
    const float* bias = (const float*)d_in[2];
    float* out = (float*)d_out;

    void *p_xa = nullptr, *p_wb = nullptr;
    cudaGetSymbolAddress(&p_xa, g_xa);
    cudaGetSymbolAddress(&p_wb, g_wb);

    const int n4 = MM * KK / 4;          // float4 count per tensor
    const int quarter = n4 / 4;
    const int nbx = quarter / 256;       // blocks per tensor (each does 4x)
    convert_fused_kernel<<<2 * nbx, 256>>>((const float4*)x, (const float4*)w,
                                           (uint2*)p_xa, (uint2*)p_wb,
                                           nbx, quarter);

    static bool attr_set = false;
    if (!attr_set) {
        cudaFuncSetAttribute(bingemm_kernel,
                             cudaFuncAttributeMaxDynamicSharedMemorySize, SMEM_TOTAL);
        attr_set = true;
    }

    int sms = 148;
    cudaDeviceGetAttribute(&sms, cudaDevAttrMultiProcessorCount, 0);
    const int G = 2 * sms;               // persistent grid: 2 CTAs per SM

    bingemm_kernel<<<G, THREADS, SMEM_TOTAL>>>(
        (const __half*)p_xa, (const __half*)p_wb, bias, out);
}